// round 2
// baseline (speedup 1.0000x reference)
#include <cuda_runtime.h>

#define T_LEN 1024
#define B_SZ  32
#define H_SZ  8
#define D_SZ  32
#define YD_SZ 97
#define IN_SZ 256
#define NCOL  165     // 32 (Wq) + 32 (Wk) + 97 (Wy) + 4 (wb)
#define NTHREADS 224  // 7 warps

// FWM per-step outputs (T,B,H*D) = (T*B, 256) row-major
__device__ float g_scratch[T_LEN * B_SZ * IN_SZ];

__device__ __forceinline__ float warp_softmax32(float v) {
    float m = v;
#pragma unroll
    for (int o = 16; o > 0; o >>= 1)
        m = fmaxf(m, __shfl_xor_sync(0xffffffffu, m, o));
    float e = __expf(v - m);
    float s = e;
#pragma unroll
    for (int o = 16; o > 0; o >>= 1)
        s += __shfl_xor_sync(0xffffffffu, s, o);
    return e / s;
}

__global__ __launch_bounds__(NTHREADS)
void srwm_scan_kernel(const float* __restrict__ h_in,
                      const float* __restrict__ W_y,
                      const float* __restrict__ W_q,
                      const float* __restrict__ W_k,
                      const float* __restrict__ w_b,
                      const float* __restrict__ sWy,
                      const float* __restrict__ sWq,
                      const float* __restrict__ sWk,
                      const float* __restrict__ swb,
                      const float* __restrict__ Fw)
{
    const int bh   = blockIdx.x;      // 256 chains
    const int b    = bh >> 3;         // 0..31
    const int hh   = bh & 7;          // 0..7
    const int tid  = threadIdx.x;
    const int wid  = tid >> 5;
    const int lane = tid & 31;

    __shared__ float xbuf[2][D_SZ];
    __shared__ float qsh[D_SZ], ksh[D_SZ];
    __shared__ float fqsh[D_SZ], fksh[D_SZ], fvsh[D_SZ];
    __shared__ float betash[4];
    __shared__ float fbsh;

    // State column lives in registers for the whole scan.
    float col[D_SZ];

    // ---- init state columns: weights + initial state ----
    if (tid < 32) {
#pragma unroll
        for (int d = 0; d < D_SZ; d++)
            col[d] = W_q[(hh * D_SZ + d) * D_SZ + tid]
                   + sWq[(((b * H_SZ + hh) * D_SZ) + d) * D_SZ + tid];
    } else if (tid < 64) {
        const int j = tid - 32;
#pragma unroll
        for (int d = 0; d < D_SZ; d++)
            col[d] = W_k[(hh * D_SZ + d) * D_SZ + j]
                   + sWk[(((b * H_SZ + hh) * D_SZ) + d) * D_SZ + j];
    } else if (tid < 161) {
        const int j = tid - 64;
#pragma unroll
        for (int d = 0; d < D_SZ; d++)
            col[d] = W_y[(hh * D_SZ + d) * YD_SZ + j]
                   + sWy[(((b * H_SZ + hh) * D_SZ) + d) * YD_SZ + j];
    } else if (tid < NCOL) {
        const int j = tid - 161;
#pragma unroll
        for (int d = 0; d < D_SZ; d++)
            col[d] = w_b[(hh * D_SZ + d) * 4 + j]
                   + swb[(((b * H_SZ + hh) * D_SZ) + d) * 4 + j];
    } else if (wid == 6) {
        // fast-weight memory column
#pragma unroll
        for (int d = 0; d < D_SZ; d++)
            col[d] = Fw[(((b * H_SZ + hh) * D_SZ) + d) * D_SZ + lane];
    }

    // x[0] = softmax(h[0]) computed by warp 6
    if (wid == 6) {
        float hv = h_in[(0 * B_SZ + b) * IN_SZ + hh * D_SZ + lane];
        xbuf[0][lane] = warp_softmax32(hv);
    }
    __syncthreads();

    for (int t = 0; t < T_LEN; ++t) {
        const float4* x4 = reinterpret_cast<const float4*>(xbuf[t & 1]);

        // ---- phase 1: raw = x_t @ [Wq|Wk|Wy|wb], per-warp nonlinearity ----
        if (tid < NCOL) {
            float a0 = 0.f, a1 = 0.f, a2 = 0.f, a3 = 0.f;
#pragma unroll
            for (int d4 = 0; d4 < 8; d4++) {
                float4 xv = x4[d4];
                a0 = fmaf(xv.x, col[4 * d4 + 0], a0);
                a1 = fmaf(xv.y, col[4 * d4 + 1], a1);
                a2 = fmaf(xv.z, col[4 * d4 + 2], a2);
                a3 = fmaf(xv.w, col[4 * d4 + 3], a3);
            }
            float raw = (a0 + a1) + (a2 + a3);
            if      (wid == 0) qsh[lane]  = warp_softmax32(raw);   // q
            else if (wid == 1) ksh[lane]  = warp_softmax32(raw);   // k
            else if (wid == 2) fqsh[lane] = warp_softmax32(raw);   // y[0:32]  -> fq
            else if (wid == 3) fksh[lane] = warp_softmax32(raw);   // y[32:64] -> fk
            else if (wid == 4) fvsh[lane] = raw;                   // y[64:96] -> fv
            else {  // wid == 5, tid 160..164
                float sg = 1.0f / (1.0f + __expf(-raw));
                if (lane == 0) fbsh = sg;                          // y[96] -> fb
                else           betash[lane - 1] = sg;              // beta[0..3]
            }
        }
        __syncthreads();

        // ---- phase 2: rank-1 updates (warps 0-5) + FWM (warp 6) ----
        if (tid < NCOL) {
            const float bsel = (tid < 32)  ? betash[1]
                             : (tid < 64)  ? betash[2]
                             : (tid < 161) ? betash[0]
                                           : betash[3];
            const float4* q4 = reinterpret_cast<const float4*>(qsh);
            const float4* k4 = reinterpret_cast<const float4*>(ksh);
            float vq0 = 0.f, vq1 = 0.f, vk0 = 0.f, vk1 = 0.f;
#pragma unroll
            for (int d4 = 0; d4 < 8; d4++) {
                float4 qv = q4[d4];
                float4 kv = k4[d4];
                vq0 = fmaf(qv.x, col[4 * d4 + 0], vq0);
                vq1 = fmaf(qv.y, col[4 * d4 + 1], vq1);
                vq0 = fmaf(qv.z, col[4 * d4 + 2], vq0);
                vq1 = fmaf(qv.w, col[4 * d4 + 3], vq1);
                vk0 = fmaf(kv.x, col[4 * d4 + 0], vk0);
                vk1 = fmaf(kv.y, col[4 * d4 + 1], vk1);
                vk0 = fmaf(kv.z, col[4 * d4 + 2], vk0);
                vk1 = fmaf(kv.w, col[4 * d4 + 3], vk1);
            }
            const float diff = bsel * ((vq0 + vq1) - (vk0 + vk1));
#pragma unroll
            for (int d4 = 0; d4 < 8; d4++) {
                float4 kv = k4[d4];
                col[4 * d4 + 0] = fmaf(kv.x, diff, col[4 * d4 + 0]);
                col[4 * d4 + 1] = fmaf(kv.y, diff, col[4 * d4 + 1]);
                col[4 * d4 + 2] = fmaf(kv.z, diff, col[4 * d4 + 2]);
                col[4 * d4 + 3] = fmaf(kv.w, diff, col[4 * d4 + 3]);
            }
        } else if (wid == 6) {
            const float4* fk4 = reinterpret_cast<const float4*>(fksh);
            const float4* fq4 = reinterpret_cast<const float4*>(fqsh);
            float v0 = 0.f, v1 = 0.f;
#pragma unroll
            for (int d4 = 0; d4 < 8; d4++) {
                float4 kv = fk4[d4];
                v0 = fmaf(kv.x, col[4 * d4 + 0], v0);
                v1 = fmaf(kv.y, col[4 * d4 + 1], v1);
                v0 = fmaf(kv.z, col[4 * d4 + 2], v0);
                v1 = fmaf(kv.w, col[4 * d4 + 3], v1);
            }
            const float coeff = fbsh * (fvsh[lane] - (v0 + v1));
            float o0 = 0.f, o1 = 0.f, o2 = 0.f, o3 = 0.f;
#pragma unroll
            for (int d4 = 0; d4 < 8; d4++) {
                float4 kv = fk4[d4];
                float4 qv = fq4[d4];
                col[4 * d4 + 0] = fmaf(kv.x, coeff, col[4 * d4 + 0]);
                col[4 * d4 + 1] = fmaf(kv.y, coeff, col[4 * d4 + 1]);
                col[4 * d4 + 2] = fmaf(kv.z, coeff, col[4 * d4 + 2]);
                col[4 * d4 + 3] = fmaf(kv.w, coeff, col[4 * d4 + 3]);
                o0 = fmaf(qv.x, col[4 * d4 + 0], o0);
                o1 = fmaf(qv.y, col[4 * d4 + 1], o1);
                o2 = fmaf(qv.z, col[4 * d4 + 2], o2);
                o3 = fmaf(qv.w, col[4 * d4 + 3], o3);
            }
            g_scratch[(t * B_SZ + b) * IN_SZ + hh * D_SZ + lane] =
                (o0 + o1) + (o2 + o3);
            if (t + 1 < T_LEN) {
                float hv = h_in[((t + 1) * B_SZ + b) * IN_SZ + hh * D_SZ + lane];
                xbuf[(t + 1) & 1][lane] = warp_softmax32(hv);
            }
        }
        __syncthreads();
    }
}

// ======================= output projection ==========================
// out[r, i] = h[r, i] + sum_j scratch[r, j] * W_out[i, j]
// (T*B=32768) x 256 x 256 sgemm, 128x128 tiles, 8x8 micro-tiles.
#define GBM 128
#define GBN 128
#define GBK 8

__global__ __launch_bounds__(256)
void proj_kernel(const float* __restrict__ W,
                 const float* __restrict__ Hin,
                 float* __restrict__ out)
{
    __shared__ float As[GBK][GBM];
    __shared__ float Bs[GBK][GBN];
    const int row0 = blockIdx.x * GBM;
    const int col0 = blockIdx.y * GBN;
    const int tid  = threadIdx.x;
    const int tr   = (tid / 16) * 8;
    const int tc   = (tid % 16) * 8;

    float acc[8][8];
#pragma unroll
    for (int u = 0; u < 8; u++)
#pragma unroll
        for (int v = 0; v < 8; v++) acc[u][v] = 0.f;

    const int ar = tid >> 1;          // row / column within tile (0..127)
    const int ak = (tid & 1) * 4;     // k quarter (0 or 4)

    for (int k0 = 0; k0 < IN_SZ; k0 += GBK) {
        float4 av = *reinterpret_cast<const float4*>(
            &g_scratch[(row0 + ar) * IN_SZ + k0 + ak]);
        float4 bv = *reinterpret_cast<const float4*>(
            &W[(col0 + ar) * IN_SZ + k0 + ak]);
        As[ak + 0][ar] = av.x; As[ak + 1][ar] = av.y;
        As[ak + 2][ar] = av.z; As[ak + 3][ar] = av.w;
        Bs[ak + 0][ar] = bv.x; Bs[ak + 1][ar] = bv.y;
        Bs[ak + 2][ar] = bv.z; Bs[ak + 3][ar] = bv.w;
        __syncthreads();
#pragma unroll
        for (int k = 0; k < GBK; k++) {
            float a[8], bb[8];
#pragma unroll
            for (int u = 0; u < 8; u++) a[u]  = As[k][tr + u];
#pragma unroll
            for (int v = 0; v < 8; v++) bb[v] = Bs[k][tc + v];
#pragma unroll
            for (int u = 0; u < 8; u++)
#pragma unroll
                for (int v = 0; v < 8; v++)
                    acc[u][v] = fmaf(a[u], bb[v], acc[u][v]);
        }
        __syncthreads();
    }

#pragma unroll
    for (int u = 0; u < 8; u++) {
        const int r = row0 + tr + u;
#pragma unroll
        for (int v4 = 0; v4 < 2; v4++) {
            const int c = col0 + tc + v4 * 4;
            float4 hv = *reinterpret_cast<const float4*>(&Hin[r * IN_SZ + c]);
            float4 ov;
            ov.x = hv.x + acc[u][v4 * 4 + 0];
            ov.y = hv.y + acc[u][v4 * 4 + 1];
            ov.z = hv.z + acc[u][v4 * 4 + 2];
            ov.w = hv.w + acc[u][v4 * 4 + 3];
            *reinterpret_cast<float4*>(&out[r * IN_SZ + c]) = ov;
        }
    }
}

extern "C" void kernel_launch(void* const* d_in, const int* in_sizes, int n_in,
                              void* d_out, int out_size) {
    const float* h_in  = (const float*)d_in[0];
    const float* W_y   = (const float*)d_in[1];
    const float* W_q   = (const float*)d_in[2];
    const float* W_k   = (const float*)d_in[3];
    const float* w_b   = (const float*)d_in[4];
    const float* W_out = (const float*)d_in[5];
    const float* sWy   = (const float*)d_in[6];
    const float* sWq   = (const float*)d_in[7];
    const float* sWk   = (const float*)d_in[8];
    const float* swb   = (const float*)d_in[9];
    const float* Fw    = (const float*)d_in[10];

    srwm_scan_kernel<<<B_SZ * H_SZ, NTHREADS>>>(
        h_in, W_y, W_q, W_k, w_b, sWy, sWq, sWk, swb, Fw);

    dim3 grid((T_LEN * B_SZ) / GBM, IN_SZ / GBN);
    proj_kernel<<<grid, 256>>>(W_out, h_in, (float*)d_out);
}

// round 3
// speedup vs baseline: 1.3907x; 1.3907x over previous
#include <cuda_runtime.h>

#define T_LEN 1024
#define B_SZ  32
#define H_SZ  8
#define D_SZ  32
#define YD_SZ 97
#define IN_SZ 256
#define NCOL  165     // 32 (Wq) + 32 (Wk) + 97 (Wy) + 4 (wb)
#define NTHREADS 224  // 7 warps

// FWM per-step outputs (T,B,H*D) = (T*B, 256) row-major
__device__ float g_scratch[T_LEN * B_SZ * IN_SZ];

__device__ __forceinline__ float warp_softmax32(float v) {
    float m = v;
#pragma unroll
    for (int o = 16; o > 0; o >>= 1)
        m = fmaxf(m, __shfl_xor_sync(0xffffffffu, m, o));
    float e = __expf(v - m);
    float s = e;
#pragma unroll
    for (int o = 16; o > 0; o >>= 1)
        s += __shfl_xor_sync(0xffffffffu, s, o);
    return __fdividef(e, s);
}

__global__ __launch_bounds__(NTHREADS)
void srwm_scan_kernel(const float* __restrict__ h_in,
                      const float* __restrict__ W_y,
                      const float* __restrict__ W_q,
                      const float* __restrict__ W_k,
                      const float* __restrict__ w_b,
                      const float* __restrict__ sWy,
                      const float* __restrict__ sWq,
                      const float* __restrict__ sWk,
                      const float* __restrict__ swb,
                      const float* __restrict__ Fw)
{
    const int bh   = blockIdx.x;      // 256 chains
    const int b    = bh >> 3;         // 0..31
    const int hh   = bh & 7;          // 0..7
    const int tid  = threadIdx.x;
    const int wid  = tid >> 5;
    const int lane = tid & 31;

    // Double-buffered inter-warp vectors (parity = t & 1).
    __shared__ float xbuf[2][D_SZ];
    __shared__ float qsh[2][D_SZ], ksh[2][D_SZ];
    __shared__ float fqsh[2][D_SZ], fksh[2][D_SZ], fvsh[2][D_SZ];
    __shared__ float betash[2][4];
    __shared__ float fbsh[2];

    // State column lives in registers for the whole scan.
    float col[D_SZ];

    // ---- init state columns: weights + initial state ----
    if (tid < 32) {
#pragma unroll
        for (int d = 0; d < D_SZ; d++)
            col[d] = W_q[(hh * D_SZ + d) * D_SZ + tid]
                   + sWq[(((b * H_SZ + hh) * D_SZ) + d) * D_SZ + tid];
    } else if (tid < 64) {
        const int j = tid - 32;
#pragma unroll
        for (int d = 0; d < D_SZ; d++)
            col[d] = W_k[(hh * D_SZ + d) * D_SZ + j]
                   + sWk[(((b * H_SZ + hh) * D_SZ) + d) * D_SZ + j];
    } else if (tid < 161) {
        const int j = tid - 64;
#pragma unroll
        for (int d = 0; d < D_SZ; d++)
            col[d] = W_y[(hh * D_SZ + d) * YD_SZ + j]
                   + sWy[(((b * H_SZ + hh) * D_SZ) + d) * YD_SZ + j];
    } else if (tid < NCOL) {
        const int j = tid - 161;
#pragma unroll
        for (int d = 0; d < D_SZ; d++)
            col[d] = w_b[(hh * D_SZ + d) * 4 + j]
                   + swb[(((b * H_SZ + hh) * D_SZ) + d) * 4 + j];
    } else if (wid == 6) {
        // fast-weight memory column
#pragma unroll
        for (int d = 0; d < D_SZ; d++)
            col[d] = Fw[(((b * H_SZ + hh) * D_SZ) + d) * D_SZ + lane];
    }

    // Warp 4 owns the x pipeline: x[0] now, h[1] prefetched into a register.
    float xreg = 0.f;
    const float* hbase = h_in + (size_t)b * IN_SZ + hh * D_SZ + lane;
    if (wid == 4) {
        xbuf[0][lane] = warp_softmax32(hbase[0]);
        xreg = hbase[(size_t)1 * B_SZ * IN_SZ];
    }
    float* scr_base = g_scratch + (size_t)b * IN_SZ + hh * D_SZ + lane;
    __syncthreads();

    for (int t = 0; t < T_LEN; ++t) {
        const int p = t & 1;
        const float4* x4 = reinterpret_cast<const float4*>(xbuf[p]);

        // ---- phase 1: raw = x_t @ [Wq|Wk|Wy|wb]; warp4 also preps x_{t+1};
        //      warp6 runs the (lagged) fast-weight memory for step t-1. ----
        if (tid < NCOL) {
            float a0 = 0.f, a1 = 0.f, a2 = 0.f, a3 = 0.f;
#pragma unroll
            for (int d4 = 0; d4 < 8; d4++) {
                float4 xv = x4[d4];
                a0 = fmaf(xv.x, col[4 * d4 + 0], a0);
                a1 = fmaf(xv.y, col[4 * d4 + 1], a1);
                a2 = fmaf(xv.z, col[4 * d4 + 2], a2);
                a3 = fmaf(xv.w, col[4 * d4 + 3], a3);
            }
            float raw = (a0 + a1) + (a2 + a3);
            if      (wid == 0) qsh[p][lane]  = warp_softmax32(raw);   // q
            else if (wid == 1) ksh[p][lane]  = warp_softmax32(raw);   // k
            else if (wid == 2) fqsh[p][lane] = warp_softmax32(raw);   // fq
            else if (wid == 3) fksh[p][lane] = warp_softmax32(raw);   // fk
            else if (wid == 4) {
                fvsh[p][lane] = raw;                                  // fv
                // x_{t+1} softmax + prefetch h[t+2]
                xbuf[p ^ 1][lane] = warp_softmax32(xreg);
                if (t + 2 < T_LEN)
                    xreg = hbase[(size_t)(t + 2) * B_SZ * IN_SZ];
            } else {  // wid == 5, tid 160..164
                float sg = 1.0f / (1.0f + __expf(-raw));
                if (lane == 0) fbsh[p] = sg;                          // fb
                else           betash[p][lane - 1] = sg;              // beta
            }
        } else if (wid == 6 && t > 0) {
            // FWM for step t-1 (reads parity p^1 buffers, written at t-1)
            const int pp = p ^ 1;
            const float4* fk4 = reinterpret_cast<const float4*>(fksh[pp]);
            const float4* fq4 = reinterpret_cast<const float4*>(fqsh[pp]);
            const float fbv = fbsh[pp];
            const float fvv = fvsh[pp][lane];
            float v0 = 0.f, v1 = 0.f;
#pragma unroll
            for (int d4 = 0; d4 < 8; d4++) {
                float4 kv = fk4[d4];
                v0 = fmaf(kv.x, col[4 * d4 + 0], v0);
                v1 = fmaf(kv.y, col[4 * d4 + 1], v1);
                v0 = fmaf(kv.z, col[4 * d4 + 2], v0);
                v1 = fmaf(kv.w, col[4 * d4 + 3], v1);
            }
            const float coeff = fbv * (fvv - (v0 + v1));
            float o0 = 0.f, o1 = 0.f, o2 = 0.f, o3 = 0.f;
#pragma unroll
            for (int d4 = 0; d4 < 8; d4++) {
                float4 kv = fk4[d4];
                float4 qv = fq4[d4];
                col[4 * d4 + 0] = fmaf(kv.x, coeff, col[4 * d4 + 0]);
                col[4 * d4 + 1] = fmaf(kv.y, coeff, col[4 * d4 + 1]);
                col[4 * d4 + 2] = fmaf(kv.z, coeff, col[4 * d4 + 2]);
                col[4 * d4 + 3] = fmaf(kv.w, coeff, col[4 * d4 + 3]);
                o0 = fmaf(qv.x, col[4 * d4 + 0], o0);
                o1 = fmaf(qv.y, col[4 * d4 + 1], o1);
                o2 = fmaf(qv.z, col[4 * d4 + 2], o2);
                o3 = fmaf(qv.w, col[4 * d4 + 3], o3);
            }
            scr_base[(size_t)(t - 1) * B_SZ * IN_SZ] = (o0 + o1) + (o2 + o3);
        }
        __syncthreads();   // the ONLY barrier per step

        // ---- phase 2: rank-1 SRWM updates (warps 0-5); no trailing barrier ----
        if (tid < NCOL) {
            const float bsel = betash[p][(tid < 32)  ? 1
                                        : (tid < 64)  ? 2
                                        : (tid < 161) ? 0
                                                      : 3];
            const float4* q4 = reinterpret_cast<const float4*>(qsh[p]);
            const float4* k4 = reinterpret_cast<const float4*>(ksh[p]);
            float vq0 = 0.f, vq1 = 0.f, vk0 = 0.f, vk1 = 0.f;
#pragma unroll
            for (int d4 = 0; d4 < 8; d4++) {
                float4 qv = q4[d4];
                float4 kv = k4[d4];
                vq0 = fmaf(qv.x, col[4 * d4 + 0], vq0);
                vq1 = fmaf(qv.y, col[4 * d4 + 1], vq1);
                vq0 = fmaf(qv.z, col[4 * d4 + 2], vq0);
                vq1 = fmaf(qv.w, col[4 * d4 + 3], vq1);
                vk0 = fmaf(kv.x, col[4 * d4 + 0], vk0);
                vk1 = fmaf(kv.y, col[4 * d4 + 1], vk1);
                vk0 = fmaf(kv.z, col[4 * d4 + 2], vk0);
                vk1 = fmaf(kv.w, col[4 * d4 + 3], vk1);
            }
            const float diff = bsel * ((vq0 + vq1) - (vk0 + vk1));
#pragma unroll
            for (int d4 = 0; d4 < 8; d4++) {
                float4 kv = k4[d4];
                col[4 * d4 + 0] = fmaf(kv.x, diff, col[4 * d4 + 0]);
                col[4 * d4 + 1] = fmaf(kv.y, diff, col[4 * d4 + 1]);
                col[4 * d4 + 2] = fmaf(kv.z, diff, col[4 * d4 + 2]);
                col[4 * d4 + 3] = fmaf(kv.w, diff, col[4 * d4 + 3]);
            }
        }
        // phase1(t+1) writes parity p^1 buffers; phase2(t) read parity p.
        // All cross-parity hazards are separated by the barrier above.
    }

    // Epilogue: FWM for the final step t = T-1 (parity (T-1)&1 = 1).
    if (wid == 6) {
        const int pp = (T_LEN - 1) & 1;
        const float4* fk4 = reinterpret_cast<const float4*>(fksh[pp]);
        const float4* fq4 = reinterpret_cast<const float4*>(fqsh[pp]);
        const float fbv = fbsh[pp];
        const float fvv = fvsh[pp][lane];
        float v0 = 0.f, v1 = 0.f;
#pragma unroll
        for (int d4 = 0; d4 < 8; d4++) {
            float4 kv = fk4[d4];
            v0 = fmaf(kv.x, col[4 * d4 + 0], v0);
            v1 = fmaf(kv.y, col[4 * d4 + 1], v1);
            v0 = fmaf(kv.z, col[4 * d4 + 2], v0);
            v1 = fmaf(kv.w, col[4 * d4 + 3], v1);
        }
        const float coeff = fbv * (fvv - (v0 + v1));
        float o0 = 0.f, o1 = 0.f, o2 = 0.f, o3 = 0.f;
#pragma unroll
        for (int d4 = 0; d4 < 8; d4++) {
            float4 kv = fk4[d4];
            float4 qv = fq4[d4];
            col[4 * d4 + 0] = fmaf(kv.x, coeff, col[4 * d4 + 0]);
            col[4 * d4 + 1] = fmaf(kv.y, coeff, col[4 * d4 + 1]);
            col[4 * d4 + 2] = fmaf(kv.z, coeff, col[4 * d4 + 2]);
            col[4 * d4 + 3] = fmaf(kv.w, coeff, col[4 * d4 + 3]);
            o0 = fmaf(qv.x, col[4 * d4 + 0], o0);
            o1 = fmaf(qv.y, col[4 * d4 + 1], o1);
            o2 = fmaf(qv.z, col[4 * d4 + 2], o2);
            o3 = fmaf(qv.w, col[4 * d4 + 3], o3);
        }
        scr_base[(size_t)(T_LEN - 1) * B_SZ * IN_SZ] = (o0 + o1) + (o2 + o3);
    }
}

// ======================= output projection ==========================
// out[r, i] = h[r, i] + sum_j scratch[r, j] * W_out[i, j]
// (T*B=32768) x 256 x 256 sgemm, 128x128 tiles, 8x8 micro-tiles.
#define GBM 128
#define GBN 128
#define GBK 8

__global__ __launch_bounds__(256)
void proj_kernel(const float* __restrict__ W,
                 const float* __restrict__ Hin,
                 float* __restrict__ out)
{
    __shared__ float As[GBK][GBM];
    __shared__ float Bs[GBK][GBN];
    const int row0 = blockIdx.x * GBM;
    const int col0 = blockIdx.y * GBN;
    const int tid  = threadIdx.x;
    const int tr   = (tid / 16) * 8;
    const int tc   = (tid % 16) * 8;

    float acc[8][8];
#pragma unroll
    for (int u = 0; u < 8; u++)
#pragma unroll
        for (int v = 0; v < 8; v++) acc[u][v] = 0.f;

    const int ar = tid >> 1;          // row / column within tile (0..127)
    const int ak = (tid & 1) * 4;     // k quarter (0 or 4)

    for (int k0 = 0; k0 < IN_SZ; k0 += GBK) {
        float4 av = *reinterpret_cast<const float4*>(
            &g_scratch[(row0 + ar) * IN_SZ + k0 + ak]);
        float4 bv = *reinterpret_cast<const float4*>(
            &W[(col0 + ar) * IN_SZ + k0 + ak]);
        As[ak + 0][ar] = av.x; As[ak + 1][ar] = av.y;
        As[ak + 2][ar] = av.z; As[ak + 3][ar] = av.w;
        Bs[ak + 0][ar] = bv.x; Bs[ak + 1][ar] = bv.y;
        Bs[ak + 2][ar] = bv.z; Bs[ak + 3][ar] = bv.w;
        __syncthreads();
#pragma unroll
        for (int k = 0; k < GBK; k++) {
            float a[8], bb[8];
#pragma unroll
            for (int u = 0; u < 8; u++) a[u]  = As[k][tr + u];
#pragma unroll
            for (int v = 0; v < 8; v++) bb[v] = Bs[k][tc + v];
#pragma unroll
            for (int u = 0; u < 8; u++)
#pragma unroll
                for (int v = 0; v < 8; v++)
                    acc[u][v] = fmaf(a[u], bb[v], acc[u][v]);
        }
        __syncthreads();
    }

#pragma unroll
    for (int u = 0; u < 8; u++) {
        const int r = row0 + tr + u;
#pragma unroll
        for (int v4 = 0; v4 < 2; v4++) {
            const int c = col0 + tc + v4 * 4;
            float4 hv = *reinterpret_cast<const float4*>(&Hin[r * IN_SZ + c]);
            float4 ov;
            ov.x = hv.x + acc[u][v4 * 4 + 0];
            ov.y = hv.y + acc[u][v4 * 4 + 1];
            ov.z = hv.z + acc[u][v4 * 4 + 2];
            ov.w = hv.w + acc[u][v4 * 4 + 3];
            *reinterpret_cast<float4*>(&out[r * IN_SZ + c]) = ov;
        }
    }
}

extern "C" void kernel_launch(void* const* d_in, const int* in_sizes, int n_in,
                              void* d_out, int out_size) {
    const float* h_in  = (const float*)d_in[0];
    const float* W_y   = (const float*)d_in[1];
    const float* W_q   = (const float*)d_in[2];
    const float* W_k   = (const float*)d_in[3];
    const float* w_b   = (const float*)d_in[4];
    const float* W_out = (const float*)d_in[5];
    const float* sWy   = (const float*)d_in[6];
    const float* sWq   = (const float*)d_in[7];
    const float* sWk   = (const float*)d_in[8];
    const float* swb   = (const float*)d_in[9];
    const float* Fw    = (const float*)d_in[10];

    srwm_scan_kernel<<<B_SZ * H_SZ, NTHREADS>>>(
        h_in, W_y, W_q, W_k, w_b, sWy, sWq, sWk, swb, Fw);

    dim3 grid((T_LEN * B_SZ) / GBM, IN_SZ / GBN);
    proj_kernel<<<grid, 256>>>(W_out, h_in, (float*)d_out);
}